// round 3
// baseline (speedup 1.0000x reference)
#include <cuda_runtime.h>
#include <math.h>

#define NSUP 16384
#define NQ   8192
#define DIM  256
#define NCLS 64
#define CBINS 4096
#define FBINS 8192
#define KRANK 67108864ULL  /* (NQ*NSUP)/2 */

__device__ float g_psum[NCLS*DIM];
__device__ float g_cnt[NCLS];
__device__ float g_protoT[DIM*NCLS];
__device__ float g_musum[DIM];
__device__ float g_mu[DIM];
__device__ float g_G[DIM*DIM];
__device__ float g_Y[DIM*DIM];
__device__ float g_Z[DIM*DIM];
__device__ float g_T[DIM*DIM];
__device__ float g_Y2[DIM*DIM];
__device__ float g_Z2[DIM*DIM];
__device__ float g_cnorm;
__device__ float g_muZ[DIM];
__device__ float g_gamma;
__device__ float g_lo;
__device__ unsigned long long g_below;
__device__ float g_swh[NSUP*DIM];
__device__ float g_qwh[NQ*DIM];
__device__ float g_sn[NSUP];
__device__ float g_qn[NQ];
__device__ float g_d2[(size_t)NQ*NSUP];
__device__ unsigned int g_h1[CBINS];
__device__ unsigned int g_h2[FBINS];

__device__ __forceinline__ float warp_sum(float v){
    #pragma unroll
    for (int o = 16; o; o >>= 1) v += __shfl_xor_sync(0xffffffffu, v, o);
    return v;
}
__device__ __forceinline__ float warp_max(float v){
    #pragma unroll
    for (int o = 16; o; o >>= 1) v = fmaxf(v, __shfl_xor_sync(0xffffffffu, v, o));
    return v;
}
// exp(-x), x>=0 small: FMA-pipe only (no MUFU)
__device__ __forceinline__ float exp_neg(float x){
    float t = x * 1.4426950408889634f;
    float n = rintf(t);
    float u = (t - n) * -0.6931471805599453f;
    float p = 1.9841270e-4f;
    p = fmaf(p, u, 1.3888889e-3f);
    p = fmaf(p, u, 8.3333333e-3f);
    p = fmaf(p, u, 4.1666667e-2f);
    p = fmaf(p, u, 1.6666667e-1f);
    p = fmaf(p, u, 0.5f);
    p = fmaf(p, u, 1.0f);
    p = fmaf(p, u, 1.0f);
    int ni = (int)n;
    return p * __int_as_float((127 - ni) << 23);
}
__device__ __forceinline__ float* bsel(int id){
    switch(id){ case 0: return g_Y; case 1: return g_Z; case 2: return g_T;
                case 3: return g_Y2; default: return g_Z2; }
}

extern "C" __global__ void k_zero(){
    int i = blockIdx.x*blockDim.x + threadIdx.x, st = gridDim.x*blockDim.x;
    for (int e=i; e<NCLS*DIM; e+=st) g_psum[e]=0.f;
    for (int e=i; e<NCLS;     e+=st) g_cnt[e]=0.f;
    for (int e=i; e<DIM;      e+=st) g_musum[e]=0.f;
    for (int e=i; e<DIM*DIM;  e+=st) g_G[e]=0.f;
    for (int e=i; e<CBINS;    e+=st) g_h1[e]=0u;
    for (int e=i; e<FBINS;    e+=st) g_h2[e]=0u;
    if (i==0) g_below=0ull;
}

// normalized class sums + mu partials + counts
extern "C" __global__ __launch_bounds__(256) void k_support(
        const float* __restrict__ sf, const int* __restrict__ lab){
    int w = threadIdx.x>>5, lane = threadIdx.x&31;
    int r0 = blockIdx.x * (NSUP/gridDim.x);
    float msum[8];
    #pragma unroll
    for (int t=0;t<8;t++) msum[t]=0.f;
    for (int r = r0+w; r < r0 + NSUP/gridDim.x; r += 8){
        const float* row = sf + (size_t)r*DIM;
        float x[8], ss=0.f;
        #pragma unroll
        for (int t=0;t<8;t++){ x[t]=row[lane+32*t]; ss += x[t]*x[t]; }
        ss = warp_sum(ss);
        float inv = 1.f / fmaxf(sqrtf(ss), 1e-8f);
        int lb = lab[r];
        #pragma unroll
        for (int t=0;t<8;t++){
            msum[t] += x[t];
            atomicAdd(&g_psum[lb*DIM + lane + 32*t], x[t]*inv);
        }
        if (!lane) atomicAdd(&g_cnt[lb], 1.f);
    }
    #pragma unroll
    for (int t=0;t<8;t++) atomicAdd(&g_musum[lane+32*t], msum[t]);
}

extern "C" __global__ void k_finalize(){
    int tid = threadIdx.x, w = tid>>5, lane = tid&31;
    if (tid < DIM) g_mu[tid] = g_musum[tid] * (1.f/NSUP);
    for (int c = w; c < NCLS; c += 8){
        float ic = 1.f / fmaxf(g_cnt[c], 1.f);
        float v[8], ss=0.f;
        #pragma unroll
        for (int t=0;t<8;t++){ v[t]=g_psum[c*DIM+lane+32*t]*ic; ss+=v[t]*v[t]; }
        ss = warp_sum(ss);
        float inv = 1.f / fmaxf(sqrtf(ss), 1e-8f);
        #pragma unroll
        for (int t=0;t<8;t++) g_protoT[(lane+32*t)*NCLS + c] = v[t]*inv;
    }
}

extern "C" __global__ __launch_bounds__(256) void k_logits(
        const float* __restrict__ qf, float* __restrict__ out){
    __shared__ float sq[4][260];
    __shared__ float sred[8], sinv[4], smax[8], ssum[8];
    int tid = threadIdx.x, w = tid>>5, lane = tid&31;
    int q0 = blockIdx.x*4;
    #pragma unroll
    for (int p=0;p<4;p++) sq[p][tid] = qf[(size_t)(q0+p)*DIM + tid];
    __syncthreads();
    { int row = w>>1, base = (w&1)*128;
      float s=0.f;
      #pragma unroll
      for (int t=0;t<4;t++){ float v=sq[row][base+lane+32*t]; s+=v*v; }
      s = warp_sum(s);
      if (!lane) sred[w]=s; }
    __syncthreads();
    if (tid<4) sinv[tid] = 1.f / fmaxf(sqrtf(sred[2*tid]+sred[2*tid+1]), 1e-8f);
    __syncthreads();
    int c = tid&63, qi = tid>>6;
    float acc = 0.f;
    #pragma unroll 8
    for (int k=0;k<DIM;k++) acc = fmaf(sq[qi][k], g_protoT[k*NCLS+c], acc);
    acc *= sinv[qi];
    float m = warp_max(acc);
    if (!lane) smax[w]=m;
    __syncthreads();
    m = fmaxf(smax[qi*2], smax[qi*2+1]);
    float e = expf(acc - m);
    float s = warp_sum(e);
    if (!lane) ssum[w]=s;
    __syncthreads();
    float lse = m + logf(ssum[qi*2]+ssum[qi*2+1]);
    out[(size_t)(q0+qi)*NCLS + c] = acc - lse;
}

// G += X^T X over a K-chunk
extern "C" __global__ __launch_bounds__(256) void k_covgemm(const float* __restrict__ X){
    __shared__ float Xa[16][68], Xb[16][68];
    int tid = threadIdx.x, tx = tid&15, ty = tid>>4;
    int i0 = blockIdx.y*64, j0 = blockIdx.x*64;
    int chunk = NSUP/gridDim.z, rb = blockIdx.z*chunk;
    float acc[4][4] = {};
    for (int r = rb; r < rb+chunk; r += 16){
        #pragma unroll
        for (int p=0;p<4;p++){
            int lin = tid + p*256, rr = lin>>6, c = lin&63;
            Xa[rr][c] = X[(size_t)(r+rr)*DIM + i0 + c];
            Xb[rr][c] = X[(size_t)(r+rr)*DIM + j0 + c];
        }
        __syncthreads();
        #pragma unroll
        for (int kk=0;kk<16;kk++){
            float a[4], b[4];
            #pragma unroll
            for (int u=0;u<4;u++){ a[u]=Xa[kk][ty*4+u]; b[u]=Xb[kk][tx*4+u]; }
            #pragma unroll
            for (int u=0;u<4;u++)
                #pragma unroll
                for (int v=0;v<4;v++) acc[u][v]=fmaf(a[u],b[v],acc[u][v]);
        }
        __syncthreads();
    }
    #pragma unroll
    for (int u=0;u<4;u++)
        #pragma unroll
        for (int v=0;v<4;v++)
            atomicAdd(&g_G[(i0+ty*4+u)*DIM + j0+tx*4+v], acc[u][v]);
}

// cov (into g_T as scratch), trace-normalize, init Y,Z
extern "C" __global__ void k_covfin(){
    __shared__ float red[256];
    int tid = threadIdx.x;
    float tr = 0.f;
    for (int e=tid; e<DIM*DIM; e+=256){
        int i = e>>8, j = e&255;
        float v = (g_G[e] - (float)NSUP*g_mu[i]*g_mu[j]) * (1.f/(NSUP-1));
        if (i==j){ v += 1e-4f; tr += v; }
        g_T[e] = v;
    }
    red[tid]=tr; __syncthreads();
    for (int s=128;s;s>>=1){ if(tid<s) red[tid]+=red[tid+s]; __syncthreads(); }
    if (!tid) g_cnorm = red[0]*(1.f/DIM);
    __syncthreads();
    float ic = 1.f/g_cnorm;
    for (int e=tid; e<DIM*DIM; e+=256){
        int i=e>>8, j=e&255;
        g_Y[e] = g_T[e]*ic;
        g_Z[e] = (i==j)?1.f:0.f;
    }
}

// 256^3 matmul; mode0: C = 1.5I - 0.5*(A@B)
extern "C" __global__ __launch_bounds__(256) void k_mm256(int ia,int ib,int ic,int mode){
    const float* A = bsel(ia); const float* B = bsel(ib); float* C = bsel(ic);
    __shared__ float As[32][33], Bs[32][33];
    int tid = threadIdx.x, tx = tid&15, ty = tid>>4;
    int j0 = blockIdx.x*32, i0 = blockIdx.y*32;
    float a00=0,a01=0,a10=0,a11=0;
    for (int k0=0;k0<DIM;k0+=32){
        #pragma unroll
        for (int p=0;p<4;p++){
            int lin = tid+p*256, r = lin>>5, c = lin&31;
            As[r][c] = A[(i0+r)*DIM + k0+c];
            Bs[r][c] = B[(k0+r)*DIM + j0+c];
        }
        __syncthreads();
        #pragma unroll
        for (int kk=0;kk<32;kk++){
            float x0=As[ty*2][kk], x1=As[ty*2+1][kk];
            float y0=Bs[kk][tx*2], y1=Bs[kk][tx*2+1];
            a00=fmaf(x0,y0,a00); a01=fmaf(x0,y1,a01);
            a10=fmaf(x1,y0,a10); a11=fmaf(x1,y1,a11);
        }
        __syncthreads();
    }
    int i = i0+ty*2, j = j0+tx*2;
    float o[2][2] = {{a00,a01},{a10,a11}};
    #pragma unroll
    for (int u=0;u<2;u++)
        #pragma unroll
        for (int v=0;v<2;v++){
            float val = o[u][v];
            if (mode==0) val = ((i+u==j+v)?1.5f:0.f) - 0.5f*val;
            C[(i+u)*DIM + j+v] = val;
        }
}

extern "C" __global__ void k_muZ(int zid){
    const float* Z = bsel(zid);
    int j = threadIdx.x;
    float s = 0.f;
    for (int k=0;k<DIM;k++) s = fmaf(g_mu[k], Z[k*DIM+j], s);
    g_muZ[j] = s;
}

// W = (X@Z - muZ) * rsqrt(cnorm); wsel 0->swh, 1->qwh
extern "C" __global__ __launch_bounds__(256) void k_whiten(
        const float* __restrict__ Xin, int zid, int wsel){
    const float* M = bsel(zid);
    float* Wout = wsel ? g_qwh : g_swh;
    __shared__ float Xs[16][132], Ms[16][68];
    int tid = threadIdx.x, tx = tid&15, ty = tid>>4;
    int m0 = blockIdx.y*128, j0 = blockIdx.x*64;
    float acc[8][4] = {};
    for (int k0=0;k0<DIM;k0+=16){
        #pragma unroll
        for (int p=0;p<2;p++){
            int lin = tid+p*256, m = lin>>2, c4 = (lin&3)*4;
            float4 v = *(const float4*)(Xin + (size_t)(m0+m)*DIM + k0 + c4);
            Xs[c4][m]=v.x; Xs[c4+1][m]=v.y; Xs[c4+2][m]=v.z; Xs[c4+3][m]=v.w;
        }
        { int r = tid>>4, c4 = (tid&15)*4;
          *(float4*)&Ms[r][c4] = *(const float4*)(M + (k0+r)*DIM + j0 + c4); }
        __syncthreads();
        #pragma unroll
        for (int kk=0;kk<16;kk++){
            float av[8], bv[4];
            #pragma unroll
            for (int u=0;u<8;u++) av[u]=Xs[kk][ty*8+u];
            #pragma unroll
            for (int v=0;v<4;v++) bv[v]=Ms[kk][tx*4+v];
            #pragma unroll
            for (int u=0;u<8;u++)
                #pragma unroll
                for (int v=0;v<4;v++) acc[u][v]=fmaf(av[u],bv[v],acc[u][v]);
        }
        __syncthreads();
    }
    float rs = 1.f / sqrtf(g_cnorm);
    float mz[4];
    #pragma unroll
    for (int v=0;v<4;v++) mz[v] = g_muZ[j0+tx*4+v];
    #pragma unroll
    for (int u=0;u<8;u++){
        float4 o;
        o.x=(acc[u][0]-mz[0])*rs; o.y=(acc[u][1]-mz[1])*rs;
        o.z=(acc[u][2]-mz[2])*rs; o.w=(acc[u][3]-mz[3])*rs;
        *(float4*)(Wout + (size_t)(m0+ty*8+u)*DIM + j0 + tx*4) = o;
    }
}

extern "C" __global__ void k_rownorm(int which){
    const float* W = which ? g_qwh : g_swh;
    float* out = which ? g_qn : g_sn;
    int gw = (blockIdx.x*blockDim.x + threadIdx.x)>>5, lane = threadIdx.x&31;
    const float* row = W + (size_t)gw*DIM;
    float ss = 0.f;
    #pragma unroll
    for (int t=0;t<8;t++){ float v=row[lane+32*t]; ss+=v*v; }
    ss = warp_sum(ss);
    if (!lane) out[gw] = ss;
}

// d2 = clip(qn+sn-2 Q@S^T, 0); 128x128 tiles, 8x8 micro (split 4+4)
// NOTE: reads g_qwh/g_swh as device globals directly — device symbols must
// NOT be passed as host-side kernel args (host shadow address + GB300 ATS
// silently reads host memory).
extern "C" __global__ __launch_bounds__(256) void k_d2(){
    const float* __restrict__ Q = g_qwh;
    const float* __restrict__ S = g_swh;
    __shared__ float Qs[16][132], Ss[16][132];
    int tid = threadIdx.x, tx = tid&15, ty = tid>>4;
    int n0 = blockIdx.x*128, m0 = blockIdx.y*128;
    float acc[8][8] = {};
    for (int k0=0;k0<DIM;k0+=16){
        #pragma unroll
        for (int p=0;p<2;p++){
            int lin = tid+p*256, r = lin>>2, c4 = (lin&3)*4;
            float4 q4 = *(const float4*)(Q + (size_t)(m0+r)*DIM + k0 + c4);
            Qs[c4][r]=q4.x; Qs[c4+1][r]=q4.y; Qs[c4+2][r]=q4.z; Qs[c4+3][r]=q4.w;
            float4 s4 = *(const float4*)(S + (size_t)(n0+r)*DIM + k0 + c4);
            Ss[c4][r]=s4.x; Ss[c4+1][r]=s4.y; Ss[c4+2][r]=s4.z; Ss[c4+3][r]=s4.w;
        }
        __syncthreads();
        #pragma unroll
        for (int kk=0;kk<16;kk++){
            float a[8], b[8];
            #pragma unroll
            for (int u=0;u<4;u++){ a[u]=Qs[kk][ty*4+u]; a[u+4]=Qs[kk][64+ty*4+u]; }
            #pragma unroll
            for (int v=0;v<4;v++){ b[v]=Ss[kk][tx*4+v]; b[v+4]=Ss[kk][64+tx*4+v]; }
            #pragma unroll
            for (int u=0;u<8;u++)
                #pragma unroll
                for (int v=0;v<8;v++) acc[u][v]=fmaf(a[u],b[v],acc[u][v]);
        }
        __syncthreads();
    }
    float snv[8];
    #pragma unroll
    for (int v=0;v<4;v++){ snv[v]=g_sn[n0+tx*4+v]; snv[v+4]=g_sn[n0+64+tx*4+v]; }
    #pragma unroll
    for (int ui=0;ui<2;ui++)
        #pragma unroll
        for (int u=0;u<4;u++){
            int row = m0 + ui*64 + ty*4 + u;
            float qn = g_qn[row];
            float* dst = g_d2 + (size_t)row*NSUP + n0;
            #pragma unroll
            for (int vi=0;vi<2;vi++){
                float4 o;
                o.x = fmaxf(qn+snv[vi*4+0]-2.f*acc[ui*4+u][vi*4+0], 0.f);
                o.y = fmaxf(qn+snv[vi*4+1]-2.f*acc[ui*4+u][vi*4+1], 0.f);
                o.z = fmaxf(qn+snv[vi*4+2]-2.f*acc[ui*4+u][vi*4+2], 0.f);
                o.w = fmaxf(qn+snv[vi*4+3]-2.f*acc[ui*4+u][vi*4+3], 0.f);
                *(float4*)(dst + vi*64 + tx*4) = o;
            }
        }
}

extern "C" __global__ void k_hist(){
    __shared__ unsigned int h[CBINS];
    for (int b=threadIdx.x; b<CBINS; b+=blockDim.x) h[b]=0u;
    __syncthreads();
    size_t i = (size_t)blockIdx.x*blockDim.x + threadIdx.x;
    size_t st = (size_t)gridDim.x*blockDim.x;
    for (; i < (size_t)NQ*NSUP; i += st){
        int b = (int)(g_d2[i]*2.0f);
        if (b > CBINS-1) b = CBINS-1;
        atomicAdd(&h[b], 1u);
    }
    __syncthreads();
    for (int b=threadIdx.x; b<CBINS; b+=blockDim.x)
        if (h[b]) atomicAdd(&g_h1[b], h[b]);
}

extern "C" __global__ void k_scan1(){
    unsigned long long cum = 0ull;
    for (int b=0;b<CBINS;b++){
        unsigned long long nxt = cum + g_h1[b];
        if (nxt >= KRANK){ g_lo = b*0.5f; g_below = cum; return; }
        cum = nxt;
    }
}

extern "C" __global__ void k_hist2(){
    __shared__ unsigned int h[FBINS];
    for (int b=threadIdx.x; b<FBINS; b+=blockDim.x) h[b]=0u;
    __syncthreads();
    float lo = g_lo;
    size_t i = (size_t)blockIdx.x*blockDim.x + threadIdx.x;
    size_t st = (size_t)gridDim.x*blockDim.x;
    for (; i < (size_t)NQ*NSUP; i += st){
        int b = (int)((g_d2[i]-lo)*16384.0f);
        if (b >= 0 && b < FBINS) atomicAdd(&h[b], 1u);
    }
    __syncthreads();
    for (int b=threadIdx.x; b<FBINS; b+=blockDim.x)
        if (h[b]) atomicAdd(&g_h2[b], h[b]);
}

extern "C" __global__ void k_scan2(){
    unsigned long long cum = g_below;
    for (int b=0;b<FBINS;b++){
        cum += g_h2[b];
        if (cum >= KRANK){
            float med = g_lo + (b+0.5f)*(0.5f/FBINS);
            g_gamma = 1.f/(med + 1e-6f);
            return;
        }
    }
    g_gamma = 1.f/(g_lo + 1e-6f);
}

extern "C" __global__ __launch_bounds__(256) void k_pred(
        const float* __restrict__ sv, float* __restrict__ out){
    __shared__ float r1[256], r2[256];
    int q = blockIdx.x, tid = threadIdx.x;
    float gamma = g_gamma;
    const float* row = g_d2 + (size_t)q*NSUP;
    float sw=0.f, swv=0.f;
    for (int i=tid; i<NSUP; i+=256){
        float wgt = exp_neg(gamma*row[i]);
        sw += wgt; swv += wgt*sv[i];
    }
    r1[tid]=sw; r2[tid]=swv; __syncthreads();
    for (int s=128;s;s>>=1){ if(tid<s){r1[tid]+=r1[tid+s]; r2[tid]+=r2[tid+s];} __syncthreads(); }
    if (!tid) out[(size_t)NQ*NCLS + q] = r2[0]/r1[0];
}

extern "C" void kernel_launch(void* const* d_in, const int* in_sizes, int n_in,
                              void* d_out, int out_size){
    const float* sf  = (const float*)d_in[0];
    const int*   lab = (const int*)  d_in[1];
    const float* sv  = (const float*)d_in[2];
    const float* qf  = (const float*)d_in[3];
    float* out = (float*)d_out;
    (void)in_sizes; (void)n_in; (void)out_size;

    k_zero<<<256,256>>>();
    k_support<<<128,256>>>(sf, lab);
    k_covgemm<<<dim3(4,4,32),256>>>(sf);
    k_finalize<<<1,256>>>();
    k_logits<<<NQ/4,256>>>(qf, out);
    k_covfin<<<1,256>>>();
    // Newton-Schulz: Y=0,Z=1,T=2,Y2=3,Z2=4
    int py=0, pz=1, py2=3, pz2=4;
    for (int it=0; it<8; it++){
        k_mm256<<<dim3(8,8),256>>>(pz, py, 2, 0);   // T = 1.5I - 0.5 Z@Y
        k_mm256<<<dim3(8,8),256>>>(py, 2, py2, 1);  // Y' = Y@T
        k_mm256<<<dim3(8,8),256>>>(2, pz, pz2, 1);  // Z' = T@Z
        int t = py; py = py2; py2 = t;
        t = pz; pz = pz2; pz2 = t;
    }
    k_muZ<<<1,256>>>(pz);
    k_whiten<<<dim3(4,NSUP/128),256>>>(sf, pz, 0);
    k_whiten<<<dim3(4,NQ/128),256>>>(qf, pz, 1);
    k_rownorm<<<NSUP/8,256>>>(0);
    k_rownorm<<<NQ/8,256>>>(1);
    k_d2<<<dim3(NSUP/128,NQ/128),256>>>();
    k_hist<<<2048,256>>>();
    k_scan1<<<1,1>>>();
    k_hist2<<<2048,256>>>();
    k_scan2<<<1,1>>>();
    k_pred<<<NQ,256>>>(sv, out);
}

// round 4
// speedup vs baseline: 1.1596x; 1.1596x over previous
#include <cuda_runtime.h>
#include <math.h>

#define NSUP 16384
#define NQ   8192
#define DIM  256
#define NCLS 64
#define CBINS 1024
#define FBINS 8192
#define KRANK 67108864ULL  /* (NQ*NSUP)/2 */

__device__ float g_psum[NCLS*DIM];
__device__ float g_cnt[NCLS];
__device__ float g_protoT[DIM*NCLS];
__device__ float g_musum[DIM];
__device__ float g_mu[DIM];
__device__ float g_G[DIM*DIM];
__device__ float g_Y[DIM*DIM];
__device__ float g_Z[DIM*DIM];
__device__ float g_T[DIM*DIM];
__device__ float g_Y2[DIM*DIM];
__device__ float g_Z2[DIM*DIM];
__device__ float g_cnorm;
__device__ float g_muZ[DIM];
__device__ float g_gamma;
__device__ float g_lo;
__device__ unsigned long long g_below;
__device__ float g_swh[NSUP*DIM];
__device__ float g_qwh[NQ*DIM];
__device__ float g_sn[NSUP];
__device__ float g_qn[NQ];
__device__ float g_d2[(size_t)NQ*NSUP];
__device__ unsigned int g_h1[CBINS];
__device__ unsigned int g_h2[FBINS];

__device__ __forceinline__ float warp_sum(float v){
    #pragma unroll
    for (int o = 16; o; o >>= 1) v += __shfl_xor_sync(0xffffffffu, v, o);
    return v;
}
__device__ __forceinline__ float warp_max(float v){
    #pragma unroll
    for (int o = 16; o; o >>= 1) v = fmaxf(v, __shfl_xor_sync(0xffffffffu, v, o));
    return v;
}
// packed fp32x2 fma: d = a*b + d (Blackwell FFMA2; only reachable via PTX)
__device__ __forceinline__ void ffma2(unsigned long long &d,
                                      unsigned long long a,
                                      unsigned long long b){
    asm("fma.rn.f32x2 %0, %1, %2, %0;" : "+l"(d) : "l"(a), "l"(b));
}
__device__ __forceinline__ unsigned long long dup2(float x){
    unsigned long long r;
    asm("mov.b64 %0, {%1, %1};" : "=l"(r) : "f"(x));
    return r;
}
__device__ __forceinline__ float2 unpk(unsigned long long x){
    float2 f;
    f.x = __uint_as_float((unsigned int)x);
    f.y = __uint_as_float((unsigned int)(x >> 32));
    return f;
}
// exp(-x), x>=0 small: FMA-pipe only (no MUFU)
__device__ __forceinline__ float exp_neg(float x){
    float t = x * 1.4426950408889634f;
    float n = rintf(t);
    float u = (t - n) * -0.6931471805599453f;
    float p = 1.9841270e-4f;
    p = fmaf(p, u, 1.3888889e-3f);
    p = fmaf(p, u, 8.3333333e-3f);
    p = fmaf(p, u, 4.1666667e-2f);
    p = fmaf(p, u, 1.6666667e-1f);
    p = fmaf(p, u, 0.5f);
    p = fmaf(p, u, 1.0f);
    p = fmaf(p, u, 1.0f);
    int ni = (int)n;
    return p * __int_as_float((127 - ni) << 23);
}
__device__ __forceinline__ float* bsel(int id){
    switch(id){ case 0: return g_Y; case 1: return g_Z; case 2: return g_T;
                case 3: return g_Y2; default: return g_Z2; }
}

extern "C" __global__ void k_zero(){
    int i = blockIdx.x*blockDim.x + threadIdx.x, st = gridDim.x*blockDim.x;
    for (int e=i; e<NCLS*DIM; e+=st) g_psum[e]=0.f;
    for (int e=i; e<NCLS;     e+=st) g_cnt[e]=0.f;
    for (int e=i; e<DIM;      e+=st) g_musum[e]=0.f;
    for (int e=i; e<DIM*DIM;  e+=st) g_G[e]=0.f;
    for (int e=i; e<CBINS;    e+=st) g_h1[e]=0u;
    for (int e=i; e<FBINS;    e+=st) g_h2[e]=0u;
    if (i==0) g_below=0ull;
}

extern "C" __global__ __launch_bounds__(256) void k_support(
        const float* __restrict__ sf, const int* __restrict__ lab){
    int w = threadIdx.x>>5, lane = threadIdx.x&31;
    int r0 = blockIdx.x * (NSUP/gridDim.x);
    float msum[8];
    #pragma unroll
    for (int t=0;t<8;t++) msum[t]=0.f;
    for (int r = r0+w; r < r0 + NSUP/gridDim.x; r += 8){
        const float* row = sf + (size_t)r*DIM;
        float x[8], ss=0.f;
        #pragma unroll
        for (int t=0;t<8;t++){ x[t]=row[lane+32*t]; ss += x[t]*x[t]; }
        ss = warp_sum(ss);
        float inv = 1.f / fmaxf(sqrtf(ss), 1e-8f);
        int lb = lab[r];
        #pragma unroll
        for (int t=0;t<8;t++){
            msum[t] += x[t];
            atomicAdd(&g_psum[lb*DIM + lane + 32*t], x[t]*inv);
        }
        if (!lane) atomicAdd(&g_cnt[lb], 1.f);
    }
    #pragma unroll
    for (int t=0;t<8;t++) atomicAdd(&g_musum[lane+32*t], msum[t]);
}

extern "C" __global__ void k_finalize(){
    int tid = threadIdx.x, w = tid>>5, lane = tid&31;
    if (tid < DIM) g_mu[tid] = g_musum[tid] * (1.f/NSUP);
    for (int c = w; c < NCLS; c += 8){
        float ic = 1.f / fmaxf(g_cnt[c], 1.f);
        float v[8], ss=0.f;
        #pragma unroll
        for (int t=0;t<8;t++){ v[t]=g_psum[c*DIM+lane+32*t]*ic; ss+=v[t]*v[t]; }
        ss = warp_sum(ss);
        float inv = 1.f / fmaxf(sqrtf(ss), 1e-8f);
        #pragma unroll
        for (int t=0;t<8;t++) g_protoT[(lane+32*t)*NCLS + c] = v[t]*inv;
    }
}

extern "C" __global__ __launch_bounds__(256) void k_logits(
        const float* __restrict__ qf, float* __restrict__ out){
    __shared__ float sq[4][260];
    __shared__ float sred[8], sinv[4], smax[8], ssum[8];
    int tid = threadIdx.x, w = tid>>5, lane = tid&31;
    int q0 = blockIdx.x*4;
    #pragma unroll
    for (int p=0;p<4;p++) sq[p][tid] = qf[(size_t)(q0+p)*DIM + tid];
    __syncthreads();
    { int row = w>>1, base = (w&1)*128;
      float s=0.f;
      #pragma unroll
      for (int t=0;t<4;t++){ float v=sq[row][base+lane+32*t]; s+=v*v; }
      s = warp_sum(s);
      if (!lane) sred[w]=s; }
    __syncthreads();
    if (tid<4) sinv[tid] = 1.f / fmaxf(sqrtf(sred[2*tid]+sred[2*tid+1]), 1e-8f);
    __syncthreads();
    int c = tid&63, qi = tid>>6;
    float acc = 0.f;
    #pragma unroll 8
    for (int k=0;k<DIM;k++) acc = fmaf(sq[qi][k], g_protoT[k*NCLS+c], acc);
    acc *= sinv[qi];
    float m = warp_max(acc);
    if (!lane) smax[w]=m;
    __syncthreads();
    m = fmaxf(smax[qi*2], smax[qi*2+1]);
    float e = expf(acc - m);
    float s = warp_sum(e);
    if (!lane) ssum[w]=s;
    __syncthreads();
    float lse = m + logf(ssum[qi*2]+ssum[qi*2+1]);
    out[(size_t)(q0+qi)*NCLS + c] = acc - lse;
}

extern "C" __global__ __launch_bounds__(256) void k_covgemm(const float* __restrict__ X){
    __shared__ float Xa[16][68], Xb[16][68];
    int tid = threadIdx.x, tx = tid&15, ty = tid>>4;
    int i0 = blockIdx.y*64, j0 = blockIdx.x*64;
    int chunk = NSUP/gridDim.z, rb = blockIdx.z*chunk;
    float acc[4][4] = {};
    for (int r = rb; r < rb+chunk; r += 16){
        #pragma unroll
        for (int p=0;p<4;p++){
            int lin = tid + p*256, rr = lin>>6, c = lin&63;
            Xa[rr][c] = X[(size_t)(r+rr)*DIM + i0 + c];
            Xb[rr][c] = X[(size_t)(r+rr)*DIM + j0 + c];
        }
        __syncthreads();
        #pragma unroll
        for (int kk=0;kk<16;kk++){
            float a[4], b[4];
            #pragma unroll
            for (int u=0;u<4;u++){ a[u]=Xa[kk][ty*4+u]; b[u]=Xb[kk][tx*4+u]; }
            #pragma unroll
            for (int u=0;u<4;u++)
                #pragma unroll
                for (int v=0;v<4;v++) acc[u][v]=fmaf(a[u],b[v],acc[u][v]);
        }
        __syncthreads();
    }
    #pragma unroll
    for (int u=0;u<4;u++)
        #pragma unroll
        for (int v=0;v<4;v++)
            atomicAdd(&g_G[(i0+ty*4+u)*DIM + j0+tx*4+v], acc[u][v]);
}

extern "C" __global__ void k_covfin(){
    __shared__ float red[256];
    int tid = threadIdx.x;
    float tr = 0.f;
    for (int e=tid; e<DIM*DIM; e+=256){
        int i = e>>8, j = e&255;
        float v = (g_G[e] - (float)NSUP*g_mu[i]*g_mu[j]) * (1.f/(NSUP-1));
        if (i==j){ v += 1e-4f; tr += v; }
        g_T[e] = v;
    }
    red[tid]=tr; __syncthreads();
    for (int s=128;s;s>>=1){ if(tid<s) red[tid]+=red[tid+s]; __syncthreads(); }
    if (!tid) g_cnorm = red[0]*(1.f/DIM);
    __syncthreads();
    float ic = 1.f/g_cnorm;
    for (int e=tid; e<DIM*DIM; e+=256){
        int i=e>>8, j=e&255;
        g_Y[e] = g_T[e]*ic;
        g_Z[e] = (i==j)?1.f:0.f;
    }
}

// 256^3 matmul; mode0: C = 1.5I - 0.5*(A@B)
extern "C" __global__ __launch_bounds__(256) void k_mm256(int ia,int ib,int ic,int mode){
    const float* A = bsel(ia); const float* B = bsel(ib); float* C = bsel(ic);
    __shared__ float As[32][33], Bs[32][33];
    int tid = threadIdx.x, tx = tid&15, ty = tid>>4;
    int j0 = blockIdx.x*32, i0 = blockIdx.y*32;
    float a00=0,a01=0,a10=0,a11=0;
    for (int k0=0;k0<DIM;k0+=32){
        #pragma unroll
        for (int p=0;p<4;p++){
            int lin = tid+p*256, r = lin>>5, c = lin&31;
            As[r][c] = A[(i0+r)*DIM + k0+c];
            Bs[r][c] = B[(k0+r)*DIM + j0+c];
        }
        __syncthreads();
        #pragma unroll
        for (int kk=0;kk<32;kk++){
            float x0=As[ty*2][kk], x1=As[ty*2+1][kk];
            float y0=Bs[kk][tx*2], y1=Bs[kk][tx*2+1];
            a00=fmaf(x0,y0,a00); a01=fmaf(x0,y1,a01);
            a10=fmaf(x1,y0,a10); a11=fmaf(x1,y1,a11);
        }
        __syncthreads();
    }
    int i = i0+ty*2, j = j0+tx*2;
    float o[2][2] = {{a00,a01},{a10,a11}};
    #pragma unroll
    for (int u=0;u<2;u++)
        #pragma unroll
        for (int v=0;v<2;v++){
            float val = o[u][v];
            if (mode==0) val = ((i+u==j+v)?1.5f:0.f) - 0.5f*val;
            C[(i+u)*DIM + j+v] = val;
        }
}

// paired NS update: z==0: Y2sel = Ysel @ T ; z==1: Z2sel = T @ Zsel
extern "C" __global__ __launch_bounds__(256) void k_mm256pair(int py,int pz,int py2,int pz2){
    const float* A; const float* B; float* C;
    if (blockIdx.z == 0){ A = bsel(py); B = g_T; C = bsel(py2); }
    else                { A = g_T; B = bsel(pz); C = bsel(pz2); }
    __shared__ float As[32][33], Bs[32][33];
    int tid = threadIdx.x, tx = tid&15, ty = tid>>4;
    int j0 = blockIdx.x*32, i0 = blockIdx.y*32;
    float a00=0,a01=0,a10=0,a11=0;
    for (int k0=0;k0<DIM;k0+=32){
        #pragma unroll
        for (int p=0;p<4;p++){
            int lin = tid+p*256, r = lin>>5, c = lin&31;
            As[r][c] = A[(i0+r)*DIM + k0+c];
            Bs[r][c] = B[(k0+r)*DIM + j0+c];
        }
        __syncthreads();
        #pragma unroll
        for (int kk=0;kk<32;kk++){
            float x0=As[ty*2][kk], x1=As[ty*2+1][kk];
            float y0=Bs[kk][tx*2], y1=Bs[kk][tx*2+1];
            a00=fmaf(x0,y0,a00); a01=fmaf(x0,y1,a01);
            a10=fmaf(x1,y0,a10); a11=fmaf(x1,y1,a11);
        }
        __syncthreads();
    }
    int i = i0+ty*2, j = j0+tx*2;
    C[i*DIM + j]       = a00;
    C[i*DIM + j+1]     = a01;
    C[(i+1)*DIM + j]   = a10;
    C[(i+1)*DIM + j+1] = a11;
}

extern "C" __global__ void k_muZ(int zid){
    const float* Z = bsel(zid);
    int j = threadIdx.x;
    float s = 0.f;
    for (int k=0;k<DIM;k++) s = fmaf(g_mu[k], Z[k*DIM+j], s);
    g_muZ[j] = s;
}

extern "C" __global__ __launch_bounds__(256) void k_whiten(
        const float* __restrict__ Xin, int zid, int wsel){
    const float* M = bsel(zid);
    float* Wout = wsel ? g_qwh : g_swh;
    __shared__ float Xs[16][132], Ms[16][68];
    int tid = threadIdx.x, tx = tid&15, ty = tid>>4;
    int m0 = blockIdx.y*128, j0 = blockIdx.x*64;
    float acc[8][4] = {};
    for (int k0=0;k0<DIM;k0+=16){
        #pragma unroll
        for (int p=0;p<2;p++){
            int lin = tid+p*256, m = lin>>2, c4 = (lin&3)*4;
            float4 v = *(const float4*)(Xin + (size_t)(m0+m)*DIM + k0 + c4);
            Xs[c4][m]=v.x; Xs[c4+1][m]=v.y; Xs[c4+2][m]=v.z; Xs[c4+3][m]=v.w;
        }
        { int r = tid>>4, c4 = (tid&15)*4;
          *(float4*)&Ms[r][c4] = *(const float4*)(M + (k0+r)*DIM + j0 + c4); }
        __syncthreads();
        #pragma unroll
        for (int kk=0;kk<16;kk++){
            float av[8], bv[4];
            #pragma unroll
            for (int u=0;u<8;u++) av[u]=Xs[kk][ty*8+u];
            #pragma unroll
            for (int v=0;v<4;v++) bv[v]=Ms[kk][tx*4+v];
            #pragma unroll
            for (int u=0;u<8;u++)
                #pragma unroll
                for (int v=0;v<4;v++) acc[u][v]=fmaf(av[u],bv[v],acc[u][v]);
        }
        __syncthreads();
    }
    float rs = 1.f / sqrtf(g_cnorm);
    float mz[4];
    #pragma unroll
    for (int v=0;v<4;v++) mz[v] = g_muZ[j0+tx*4+v];
    #pragma unroll
    for (int u=0;u<8;u++){
        float4 o;
        o.x=(acc[u][0]-mz[0])*rs; o.y=(acc[u][1]-mz[1])*rs;
        o.z=(acc[u][2]-mz[2])*rs; o.w=(acc[u][3]-mz[3])*rs;
        *(float4*)(Wout + (size_t)(m0+ty*8+u)*DIM + j0 + tx*4) = o;
    }
}

extern "C" __global__ void k_rownorm(int which){
    const float* W = which ? g_qwh : g_swh;
    float* out = which ? g_qn : g_sn;
    int gw = (blockIdx.x*blockDim.x + threadIdx.x)>>5, lane = threadIdx.x&31;
    const float* row = W + (size_t)gw*DIM;
    float ss = 0.f;
    #pragma unroll
    for (int t=0;t<8;t++){ float v=row[lane+32*t]; ss+=v*v; }
    ss = warp_sum(ss);
    if (!lane) out[gw] = ss;
}

// d2 = clip(qn+sn-2 Q@S^T, 0); fp32x2 packed FMA; fused coarse histogram.
extern "C" __global__ __launch_bounds__(256) void k_d2(){
    const float* __restrict__ Q = g_qwh;
    const float* __restrict__ S = g_swh;
    __shared__ float Qs[16][132], Ss[16][132];
    __shared__ unsigned int sh[CBINS];
    int tid = threadIdx.x, tx = tid&15, ty = tid>>4;
    int n0 = blockIdx.x*128, m0 = blockIdx.y*128;
    for (int b=tid; b<CBINS; b+=256) sh[b]=0u;
    unsigned long long acc2[8][4];
    #pragma unroll
    for (int u=0;u<8;u++)
        #pragma unroll
        for (int j=0;j<4;j++) acc2[u][j]=0ull;
    for (int k0=0;k0<DIM;k0+=16){
        #pragma unroll
        for (int p=0;p<2;p++){
            int lin = tid+p*256, r = lin>>2, c4 = (lin&3)*4;
            float4 q4 = *(const float4*)(Q + (size_t)(m0+r)*DIM + k0 + c4);
            Qs[c4][r]=q4.x; Qs[c4+1][r]=q4.y; Qs[c4+2][r]=q4.z; Qs[c4+3][r]=q4.w;
            float4 s4 = *(const float4*)(S + (size_t)(n0+r)*DIM + k0 + c4);
            Ss[c4][r]=s4.x; Ss[c4+1][r]=s4.y; Ss[c4+2][r]=s4.z; Ss[c4+3][r]=s4.w;
        }
        __syncthreads();
        #pragma unroll
        for (int kk=0;kk<16;kk++){
            float4 qa = *(const float4*)&Qs[kk][ty*4];
            float4 qb = *(const float4*)&Qs[kk][64+ty*4];
            unsigned long long ad[8];
            ad[0]=dup2(qa.x); ad[1]=dup2(qa.y); ad[2]=dup2(qa.z); ad[3]=dup2(qa.w);
            ad[4]=dup2(qb.x); ad[5]=dup2(qb.y); ad[6]=dup2(qb.z); ad[7]=dup2(qb.w);
            ulonglong2 b01 = *(const ulonglong2*)&Ss[kk][tx*4];
            ulonglong2 b23 = *(const ulonglong2*)&Ss[kk][64+tx*4];
            unsigned long long bb[4] = {b01.x, b01.y, b23.x, b23.y};
            #pragma unroll
            for (int u=0;u<8;u++)
                #pragma unroll
                for (int j=0;j<4;j++) ffma2(acc2[u][j], ad[u], bb[j]);
        }
        __syncthreads();
    }
    float snv[8];
    #pragma unroll
    for (int v=0;v<4;v++){ snv[v]=g_sn[n0+tx*4+v]; snv[v+4]=g_sn[n0+64+tx*4+v]; }
    #pragma unroll
    for (int ui=0;ui<2;ui++)
        #pragma unroll
        for (int u=0;u<4;u++){
            int row = m0 + ui*64 + ty*4 + u;
            float qn = g_qn[row];
            float* dst = g_d2 + (size_t)row*NSUP + n0;
            #pragma unroll
            for (int vi=0;vi<2;vi++){
                float2 p0 = unpk(acc2[ui*4+u][vi*2+0]);
                float2 p1 = unpk(acc2[ui*4+u][vi*2+1]);
                float4 o;
                o.x = fmaxf(qn+snv[vi*4+0]-2.f*p0.x, 0.f);
                o.y = fmaxf(qn+snv[vi*4+1]-2.f*p0.y, 0.f);
                o.z = fmaxf(qn+snv[vi*4+2]-2.f*p1.x, 0.f);
                o.w = fmaxf(qn+snv[vi*4+3]-2.f*p1.y, 0.f);
                *(float4*)(dst + vi*64 + tx*4) = o;
                int b0 = (int)(o.x*0.5f); if (b0>CBINS-1) b0=CBINS-1;
                int b1 = (int)(o.y*0.5f); if (b1>CBINS-1) b1=CBINS-1;
                int b2 = (int)(o.z*0.5f); if (b2>CBINS-1) b2=CBINS-1;
                int b3 = (int)(o.w*0.5f); if (b3>CBINS-1) b3=CBINS-1;
                atomicAdd(&sh[b0],1u); atomicAdd(&sh[b1],1u);
                atomicAdd(&sh[b2],1u); atomicAdd(&sh[b3],1u);
            }
        }
    __syncthreads();
    for (int b=tid; b<CBINS; b+=256)
        if (sh[b]) atomicAdd(&g_h1[b], sh[b]);
}

extern "C" __global__ void k_scan1(){
    unsigned long long cum = 0ull;
    for (int b=0;b<CBINS;b++){
        unsigned long long nxt = cum + g_h1[b];
        if (nxt >= KRANK){ g_lo = b*2.0f; g_below = cum; return; }
        cum = nxt;
    }
}

extern "C" __global__ void k_hist2(){
    __shared__ unsigned int h[FBINS];
    for (int b=threadIdx.x; b<FBINS; b+=blockDim.x) h[b]=0u;
    __syncthreads();
    float lo = g_lo;
    size_t i = (size_t)blockIdx.x*blockDim.x + threadIdx.x;
    size_t st = (size_t)gridDim.x*blockDim.x;
    for (; i < (size_t)NQ*NSUP; i += st){
        int b = (int)((g_d2[i]-lo)*4096.0f);
        if (b >= 0 && b < FBINS) atomicAdd(&h[b], 1u);
    }
    __syncthreads();
    for (int b=threadIdx.x; b<FBINS; b+=blockDim.x)
        if (h[b]) atomicAdd(&g_h2[b], h[b]);
}

extern "C" __global__ void k_scan2(){
    unsigned long long cum = g_below;
    for (int b=0;b<FBINS;b++){
        cum += g_h2[b];
        if (cum >= KRANK){
            float med = g_lo + (b+0.5f)*(2.0f/FBINS);
            g_gamma = 1.f/(med + 1e-6f);
            return;
        }
    }
    g_gamma = 1.f/(g_lo + 1e-6f);
}

extern "C" __global__ __launch_bounds__(256) void k_pred(
        const float* __restrict__ sv, float* __restrict__ out){
    __shared__ float r1[256], r2[256];
    int q = blockIdx.x, tid = threadIdx.x;
    float gamma = g_gamma;
    const float* row = g_d2 + (size_t)q*NSUP;
    float sw=0.f, swv=0.f;
    for (int i=tid; i<NSUP; i+=256){
        float wgt = exp_neg(gamma*row[i]);
        sw += wgt; swv += wgt*sv[i];
    }
    r1[tid]=sw; r2[tid]=swv; __syncthreads();
    for (int s=128;s;s>>=1){ if(tid<s){r1[tid]+=r1[tid+s]; r2[tid]+=r2[tid+s];} __syncthreads(); }
    if (!tid) out[(size_t)NQ*NCLS + q] = r2[0]/r1[0];
}

extern "C" void kernel_launch(void* const* d_in, const int* in_sizes, int n_in,
                              void* d_out, int out_size){
    const float* sf  = (const float*)d_in[0];
    const int*   lab = (const int*)  d_in[1];
    const float* sv  = (const float*)d_in[2];
    const float* qf  = (const float*)d_in[3];
    float* out = (float*)d_out;
    (void)in_sizes; (void)n_in; (void)out_size;

    k_zero<<<256,256>>>();
    k_support<<<128,256>>>(sf, lab);
    k_covgemm<<<dim3(4,4,32),256>>>(sf);
    k_finalize<<<1,256>>>();
    k_logits<<<NQ/4,256>>>(qf, out);
    k_covfin<<<1,256>>>();
    // Newton-Schulz (6 iters): Y=0,Z=1,T=2,Y2=3,Z2=4
    int py=0, pz=1, py2=3, pz2=4;
    for (int it=0; it<6; it++){
        k_mm256<<<dim3(8,8),256>>>(pz, py, 2, 0);           // T = 1.5I - 0.5 Z@Y
        k_mm256pair<<<dim3(8,8,2),256>>>(py, pz, py2, pz2); // Y'=Y@T ; Z'=T@Z
        int t = py; py = py2; py2 = t;
        t = pz; pz = pz2; pz2 = t;
    }
    k_muZ<<<1,256>>>(pz);
    k_whiten<<<dim3(4,NSUP/128),256>>>(sf, pz, 0);
    k_whiten<<<dim3(4,NQ/128),256>>>(qf, pz, 1);
    k_rownorm<<<NSUP/8,256>>>(0);
    k_rownorm<<<NQ/8,256>>>(1);
    k_d2<<<dim3(NSUP/128,NQ/128),256>>>();
    k_scan1<<<1,1>>>();
    k_hist2<<<2048,256>>>();
    k_scan2<<<1,1>>>();
    k_pred<<<NQ,256>>>(sv, out);
}